// round 12
// baseline (speedup 1.0000x reference)
#include <cuda_runtime.h>
#include <math.h>
#include <cstdint>

// Problem constants
#define DD   2048
#define EE   64
#define NTOK 32768
#define KTOP 8

// GEMM tiling
#define BM   128       // tokens per block
#define DK   32        // D-chunk staged in smem
#define TPB  256

#define GAP_THRESH 2.5e-6f   // prob-gap flag threshold (~15 sigma of pass-1 noise)
#define LSTRIDE 66           // smem logit row stride (conflict-free, 8B-aligned)

typedef unsigned long long u64;

// flagged-token queue (device globals: allocation-free per harness rules)
__device__ int g_nflag;          // reset by router_reset each launch
__device__ int g_flags[NTOK];

__device__ __forceinline__ u64 pack2(float lo, float hi) {
    u64 r;
    asm("mov.b64 %0, {%1, %2};" : "=l"(r) : "f"(lo), "f"(hi));
    return r;
}
__device__ __forceinline__ void fma2(u64& acc, u64 a, u64 b) {
    asm("fma.rn.f32x2 %0, %1, %2, %0;" : "+l"(acc) : "l"(a), "l"(b));
}
__device__ __forceinline__ u64 add2(u64 a, u64 b) {
    u64 r;
    asm("add.rn.f32x2 %0, %1, %2;" : "=l"(r) : "l"(a), "l"(b));
    return r;
}

// ---------------------------------------------------------------------------
// Warp-collective per-token epilogue: softmax(64) -> top-8 on fp32 probs
// (ties -> lower index, = jax.lax.top_k over softmax output) -> softmax(8).
// Runs 9 selection rounds to measure the min adjacent prob gap (ranks 1..9);
// if below GAP_THRESH the token is queued for exact fp64 recompute (pass 2).
// ---------------------------------------------------------------------------
__device__ __forceinline__ void warp_topk_token(const float* lsrow, int tok,
                                                float* outw, float* outi,
                                                bool enable_flag) {
    const int lane = threadIdx.x & 31;
    const float k0 = lsrow[lane];
    const float k1 = lsrow[lane + 32];

    float m = fmaxf(k0, k1);
#pragma unroll
    for (int off = 16; off; off >>= 1) m = fmaxf(m, __shfl_xor_sync(0xffffffffu, m, off));
    const float e0 = expf(k0 - m);
    const float e1 = expf(k1 - m);
    float ssum = e0 + e1;
#pragma unroll
    for (int off = 16; off; off >>= 1) ssum += __shfl_xor_sync(0xffffffffu, ssum, off);

    float v0 = e0 / ssum, v1 = e1 / ssum;

    float selp = 0.f;
    int   seli = 0;
    float prevbv = 0.f, mingap = 1e30f;

#pragma unroll
    for (int rr = 0; rr < KTOP + 1; rr++) {
        float bv = v0;
        int   bi = lane;
        if (v1 > bv) { bv = v1; bi = lane + 32; }
#pragma unroll
        for (int off = 16; off; off >>= 1) {
            float ov = __shfl_down_sync(0xffffffffu, bv, off);
            int   oi = __shfl_down_sync(0xffffffffu, bi, off);
            if (ov > bv || (ov == bv && oi < bi)) { bv = ov; bi = oi; }
        }
        bv = __shfl_sync(0xffffffffu, bv, 0);
        bi = __shfl_sync(0xffffffffu, bi, 0);
        if (rr > 0) mingap = fminf(mingap, prevbv - bv);
        prevbv = bv;
        if (rr < KTOP && lane == rr) { selp = bv; seli = bi; }
        if (bi == lane)      v0 = -__int_as_float(0x7f800000);
        if (bi == lane + 32) v1 = -__int_as_float(0x7f800000);
    }

    if (enable_flag && lane == 0 && mingap < GAP_THRESH) {
        int idx = atomicAdd(&g_nflag, 1);
        if (idx < NTOK) g_flags[idx] = tok;    // bounds-guarded
    }

    // softmax over the 8 selected probs (lanes 0..7, descending)
    const float pm = __shfl_sync(0xffffffffu, selp, 0);
    float e  = expf(selp - pm);
    float es = e;
#pragma unroll
    for (int off = 4; off; off >>= 1) es += __shfl_xor_sync(0xffffffffu, es, off);

    if (lane < KTOP) {
        outw[(size_t)tok * KTOP + lane] = e / es;
        outi[(size_t)tok * KTOP + lane] = (float)seli;
    }
}

// ---------------------------------------------------------------------------
// Pass 1: fused GEMM + softmax/top-k. Fast accumulation (chunk-32 fresh
// inner accumulator, one packed fold per chunk; sigma_logit ~2e-7), occ=2.
// ---------------------------------------------------------------------------
__global__ __launch_bounds__(TPB, 2)
void router_gemm(const float* __restrict__ x, const float* __restrict__ w,
                 float* __restrict__ outw, float* __restrict__ outi) {
    __shared__ float sb[BM * LSTRIDE];     // union: stage (6144 f) / logits (8448 f)
    float* xs = sb;                        // [DK][BM] transposed x chunk
    float* ws = sb + DK * BM;              // [DK][EE] w chunk

    const int tid = threadIdx.x;
    const int tx  = tid & 7;               // expert octet
    const int ty  = tid >> 3;              // token quad
    const int tokBase = blockIdx.x * BM;

    u64 s[4][4];
#pragma unroll
    for (int t = 0; t < 4; t++)
#pragma unroll
        for (int j = 0; j < 4; j++) s[t][j] = 0ull;

    const int r = tid >> 1;
    const int h = tid & 1;
    const float* xptr = x + (size_t)(tokBase + r) * DD + h * 16;

    float4 rx[4], rw0, rw1;
    {
        const float4* xg = (const float4*)xptr;
#pragma unroll
        for (int i = 0; i < 4; i++) rx[i] = xg[i];
        const float4* wg = (const float4*)w;
        rw0 = wg[tid * 2];
        rw1 = wg[tid * 2 + 1];
    }

    const int NCHUNK = DD / DK;
    for (int ch = 0; ch < NCHUNK; ch++) {
        __syncthreads();
#pragma unroll
        for (int k = 0; k < 4; k++) {
            xs[(h * 16 + k * 4 + 0) * BM + r] = rx[k].x;
            xs[(h * 16 + k * 4 + 1) * BM + r] = rx[k].y;
            xs[(h * 16 + k * 4 + 2) * BM + r] = rx[k].z;
            xs[(h * 16 + k * 4 + 3) * BM + r] = rx[k].w;
        }
        {
            float4* wsp = (float4*)ws;
            wsp[tid * 2]     = rw0;
            wsp[tid * 2 + 1] = rw1;
        }
        if (ch + 1 < NCHUNK) {
            const float4* xg = (const float4*)(xptr + (ch + 1) * DK);
#pragma unroll
            for (int i = 0; i < 4; i++) rx[i] = xg[i];
            const float4* wg = (const float4*)(w + (size_t)(ch + 1) * DK * EE);
            rw0 = wg[tid * 2];
            rw1 = wg[tid * 2 + 1];
        }
        __syncthreads();

        // fresh chunk accumulator (keeps partials small: sigma stays ~2e-7)
        u64 p[4][4];
#pragma unroll
        for (int t = 0; t < 4; t++)
#pragma unroll
            for (int j = 0; j < 4; j++) p[t][j] = 0ull;

#pragma unroll
        for (int d = 0; d < DK; d++) {
            float4 av = *(const float4*)&xs[d * BM + ty * 4];
            u64 a2[4];
            a2[0] = pack2(av.x, av.x);
            a2[1] = pack2(av.y, av.y);
            a2[2] = pack2(av.z, av.z);
            a2[3] = pack2(av.w, av.w);
            ulonglong2 b01 = *(const ulonglong2*)&ws[d * EE + tx * 8];
            ulonglong2 b23 = *(const ulonglong2*)&ws[d * EE + tx * 8 + 4];
            u64 bb[4] = { b01.x, b01.y, b23.x, b23.y };
#pragma unroll
            for (int t = 0; t < 4; t++)
#pragma unroll
                for (int j = 0; j < 4; j++)
                    fma2(p[t][j], a2[t], bb[j]);
        }

#pragma unroll
        for (int t = 0; t < 4; t++)
#pragma unroll
            for (int j = 0; j < 4; j++) s[t][j] = add2(s[t][j], p[t][j]);
    }

    // ---- fused epilogue: logits -> smem, then warp-per-token top-k ----
    __syncthreads();    // done reading xs/ws; reuse sb for logits
#pragma unroll
    for (int t = 0; t < 4; t++) {
        const int ltok = ty * 4 + t;
#pragma unroll
        for (int j = 0; j < 4; j++)
            *(u64*)&sb[ltok * LSTRIDE + tx * 8 + 2 * j] = s[t][j];
    }
    __syncthreads();

    const int wid = tid >> 5;
    for (int t = 0; t < BM / 8; t++) {          // 16 tokens per warp
        const int ltok = wid * (BM / 8) + t;
        warp_topk_token(sb + ltok * LSTRIDE, tokBase + ltok, outw, outi, true);
    }
}

// ---------------------------------------------------------------------------
// Pass 2: exact fp64 recompute of flagged tokens (persistent blocks).
// fp64 accumulation -> correctly-rounded fp32 logits -> identical softmax/
// top-k semantics as the reference (ties -> lower index).
// ---------------------------------------------------------------------------
__global__ __launch_bounds__(256)
void router_fix(const float* __restrict__ x, const float* __restrict__ w,
                float* __restrict__ outw, float* __restrict__ outi) {
    __shared__ double qs[4][EE];
    __shared__ float  ls[EE];

    int n = g_nflag;
    if (n > NTOK) n = NTOK;              // bounds-guarded
    const int e = threadIdx.x & 63;
    const int q = threadIdx.x >> 6;      // d-quarter 0..3

    for (int i = blockIdx.x; i < n; i += gridDim.x) {
        const int tok = g_flags[i];
        const float* xr = x + (size_t)tok * DD + q * (DD / 4);
        const float* wr = w + (size_t)(q * (DD / 4)) * EE + e;

        double a0 = 0.0, a1 = 0.0, a2 = 0.0, a3 = 0.0;
#pragma unroll 8
        for (int d = 0; d < DD / 4; d += 4) {
            a0 = fma((double)__ldg(xr + d + 0), (double)__ldg(wr + (size_t)(d + 0) * EE), a0);
            a1 = fma((double)__ldg(xr + d + 1), (double)__ldg(wr + (size_t)(d + 1) * EE), a1);
            a2 = fma((double)__ldg(xr + d + 2), (double)__ldg(wr + (size_t)(d + 2) * EE), a2);
            a3 = fma((double)__ldg(xr + d + 3), (double)__ldg(wr + (size_t)(d + 3) * EE), a3);
        }
        qs[q][e] = (a0 + a1) + (a2 + a3);
        __syncthreads();
        if (threadIdx.x < EE) {
            double t = ((qs[0][e] + qs[1][e]) + qs[2][e]) + qs[3][e];
            ls[e] = (float)t;
        }
        __syncthreads();
        if (threadIdx.x < 32)
            warp_topk_token(ls, tok, outw, outi, false);
        __syncthreads();
    }
}

__global__ void router_reset() { g_nflag = 0; }

// ---------------------------------------------------------------------------
extern "C" void kernel_launch(void* const* d_in, const int* in_sizes, int n_in,
                              void* d_out, int out_size) {
    const float* x = (const float*)d_in[0];   // (4, 8192, 2048) f32
    const float* w = (const float*)d_in[1];   // (2048, 64) f32
    float* out  = (float*)d_out;
    float* outw = out;                          // weights: 32768*8
    float* outi = out + (size_t)NTOK * KTOP;    // indices (as float)

    router_reset<<<1, 1>>>();
    router_gemm<<<NTOK / BM, TPB>>>(x, w, outw, outi);
    router_fix<<<128, 256>>>(x, w, outw, outi);
}

// round 16
// speedup vs baseline: 1.1683x; 1.1683x over previous
#include <cuda_runtime.h>
#include <math.h>
#include <cstdint>

// Problem constants
#define DD   2048
#define EE   64
#define NTOK 32768
#define KTOP 8

// GEMM tiling
#define BM   128       // tokens per block
#define DK   32        // D-chunk staged in smem
#define TPB  512       // threads per block (16 warps)

#define GAP_THRESH 2.5e-6f   // prob-gap flag threshold (>>15 sigma of pass-1 noise)
#define LSTRIDE 66           // smem logit row stride (conflict-free, 8B-aligned)

typedef unsigned long long u64;

// flagged-token queue (device globals: allocation-free per harness rules)
__device__ int g_nflag;          // starts 0 (BSS); reset by last router_fix block
__device__ int g_done;           // completion ticket for the reset
__device__ int g_flags[NTOK];

__device__ __forceinline__ u64 pack2(float lo, float hi) {
    u64 r;
    asm("mov.b64 %0, {%1, %2};" : "=l"(r) : "f"(lo), "f"(hi));
    return r;
}
__device__ __forceinline__ void fma2(u64& acc, u64 a, u64 b) {
    asm("fma.rn.f32x2 %0, %1, %2, %0;" : "+l"(acc) : "l"(a), "l"(b));
}
__device__ __forceinline__ u64 add2(u64 a, u64 b) {
    u64 r;
    asm("add.rn.f32x2 %0, %1, %2;" : "=l"(r) : "l"(a), "l"(b));
    return r;
}

// ---------------------------------------------------------------------------
// Warp-collective per-token epilogue: softmax(64) -> top-8 on fp32 probs
// (ties -> lower index, = jax.lax.top_k over softmax output) -> softmax(8).
// 9 selection rounds measure the min adjacent prob gap (ranks 1..9); below
// GAP_THRESH the token is queued for exact fp64 recompute (pass 2).
// ---------------------------------------------------------------------------
__device__ __forceinline__ void warp_topk_token(const float* lsrow, int tok,
                                                float* outw, float* outi,
                                                bool enable_flag) {
    const int lane = threadIdx.x & 31;
    const float k0 = lsrow[lane];
    const float k1 = lsrow[lane + 32];

    float m = fmaxf(k0, k1);
#pragma unroll
    for (int off = 16; off; off >>= 1) m = fmaxf(m, __shfl_xor_sync(0xffffffffu, m, off));
    const float e0 = expf(k0 - m);
    const float e1 = expf(k1 - m);
    float ssum = e0 + e1;
#pragma unroll
    for (int off = 16; off; off >>= 1) ssum += __shfl_xor_sync(0xffffffffu, ssum, off);

    float v0 = e0 / ssum, v1 = e1 / ssum;

    float selp = 0.f;
    int   seli = 0;
    float prevbv = 0.f, mingap = 1e30f;

#pragma unroll
    for (int rr = 0; rr < KTOP + 1; rr++) {
        float bv = v0;
        int   bi = lane;
        if (v1 > bv) { bv = v1; bi = lane + 32; }
#pragma unroll
        for (int off = 16; off; off >>= 1) {
            float ov = __shfl_down_sync(0xffffffffu, bv, off);
            int   oi = __shfl_down_sync(0xffffffffu, bi, off);
            if (ov > bv || (ov == bv && oi < bi)) { bv = ov; bi = oi; }
        }
        bv = __shfl_sync(0xffffffffu, bv, 0);
        bi = __shfl_sync(0xffffffffu, bi, 0);
        if (rr > 0) mingap = fminf(mingap, prevbv - bv);
        prevbv = bv;
        if (rr < KTOP && lane == rr) { selp = bv; seli = bi; }
        if (bi == lane)      v0 = -__int_as_float(0x7f800000);
        if (bi == lane + 32) v1 = -__int_as_float(0x7f800000);
    }

    if (enable_flag && lane == 0 && mingap < GAP_THRESH) {
        int idx = atomicAdd(&g_nflag, 1);
        if (idx < NTOK) g_flags[idx] = tok;
    }

    // softmax over the 8 selected probs (lanes 0..7, descending)
    const float pm = __shfl_sync(0xffffffffu, selp, 0);
    float e  = expf(selp - pm);
    float es = e;
#pragma unroll
    for (int off = 4; off; off >>= 1) es += __shfl_xor_sync(0xffffffffu, es, off);

    if (lane < KTOP) {
        outw[(size_t)tok * KTOP + lane] = e / es;
        outi[(size_t)tok * KTOP + lane] = (float)seli;
    }
}

// ---------------------------------------------------------------------------
// Pass 1: fused GEMM + softmax/top-k. 512 threads, 2 tok x 8 exp microtile
// (s+p accumulators = 32 regs -> ~85 total, NO spills). Chunk-32 fresh inner
// accumulator, one packed fold per chunk (same numerics as the passing
// round-12 pass-1: sigma_logit ~2e-7).
// ---------------------------------------------------------------------------
__global__ __launch_bounds__(TPB, 1)
void router_gemm(const float* __restrict__ x, const float* __restrict__ w,
                 float* __restrict__ outw, float* __restrict__ outi) {
    __shared__ float sb[BM * LSTRIDE];     // union: stage (6144 f) / logits (8448 f)
    float* xs = sb;                        // [DK][BM] transposed x chunk
    float* ws = sb + DK * BM;              // [DK][EE] w chunk

    const int tid = threadIdx.x;
    const int tx  = tid & 7;               // expert octet: tx*8 .. tx*8+7
    const int ty  = tid >> 3;              // token pair:   ty*2, ty*2+1
    const int tokBase = blockIdx.x * BM;

    // s[t][j]: token ty*2+t, experts (tx*8+2j, tx*8+2j+1) packed
    u64 s[2][4];
#pragma unroll
    for (int t = 0; t < 2; t++)
#pragma unroll
        for (int j = 0; j < 4; j++) s[t][j] = 0ull;

    // x staging map: row r (0..127), 8 floats starting at h*8
    const int r = tid >> 2;
    const int h = tid & 3;
    const float* xptr = x + (size_t)(tokBase + r) * DD + h * 8;

    float4 rx0, rx1, rw;
    {
        const float4* xg = (const float4*)xptr;
        rx0 = xg[0]; rx1 = xg[1];
        rw  = ((const float4*)w)[tid];     // chunk contiguous: 512*4 = 2048 floats
    }

    const int NCHUNK = DD / DK;   // 64
    for (int ch = 0; ch < NCHUNK; ch++) {
        __syncthreads();
        // stage x transposed: xs[d][token]
        {
            const int dbase = h * 8;
            xs[(dbase + 0) * BM + r] = rx0.x;
            xs[(dbase + 1) * BM + r] = rx0.y;
            xs[(dbase + 2) * BM + r] = rx0.z;
            xs[(dbase + 3) * BM + r] = rx0.w;
            xs[(dbase + 4) * BM + r] = rx1.x;
            xs[(dbase + 5) * BM + r] = rx1.y;
            xs[(dbase + 6) * BM + r] = rx1.z;
            xs[(dbase + 7) * BM + r] = rx1.w;
            ((float4*)ws)[tid] = rw;
        }
        // prefetch next chunk (hidden under compute)
        if (ch + 1 < NCHUNK) {
            const float4* xg = (const float4*)(xptr + (ch + 1) * DK);
            rx0 = xg[0]; rx1 = xg[1];
            rw  = ((const float4*)(w + (size_t)(ch + 1) * DK * EE))[tid];
        }
        __syncthreads();

        // fresh chunk accumulator (keeps partials small: sigma ~2e-7)
        u64 p[2][4];
#pragma unroll
        for (int t = 0; t < 2; t++)
#pragma unroll
            for (int j = 0; j < 4; j++) p[t][j] = 0ull;

#pragma unroll
        for (int d = 0; d < DK; d++) {
            float2 av = *(const float2*)&xs[d * BM + ty * 2];
            const u64 a0 = pack2(av.x, av.x);
            const u64 a1 = pack2(av.y, av.y);
            ulonglong2 b01 = *(const ulonglong2*)&ws[d * EE + tx * 8];
            ulonglong2 b23 = *(const ulonglong2*)&ws[d * EE + tx * 8 + 4];
            u64 bb[4] = { b01.x, b01.y, b23.x, b23.y };
#pragma unroll
            for (int j = 0; j < 4; j++) {
                fma2(p[0][j], a0, bb[j]);
                fma2(p[1][j], a1, bb[j]);
            }
        }

#pragma unroll
        for (int t = 0; t < 2; t++)
#pragma unroll
            for (int j = 0; j < 4; j++) s[t][j] = add2(s[t][j], p[t][j]);
    }

    // ---- fused epilogue: logits -> smem, then warp-per-token top-k ----
    __syncthreads();    // done reading xs/ws; reuse sb for logits
#pragma unroll
    for (int t = 0; t < 2; t++) {
        const int ltok = ty * 2 + t;
#pragma unroll
        for (int j = 0; j < 4; j++)
            *(u64*)&sb[ltok * LSTRIDE + tx * 8 + 2 * j] = s[t][j];
    }
    __syncthreads();

    const int wid = tid >> 5;                   // 16 warps
    for (int t = 0; t < BM / 16; t++) {         // 8 tokens per warp
        const int ltok = wid * (BM / 16) + t;
        warp_topk_token(sb + ltok * LSTRIDE, tokBase + ltok, outw, outi, true);
    }
}

// ---------------------------------------------------------------------------
// Pass 2: exact fp64 recompute of flagged tokens. fp64 accumulation ->
// correctly-rounded fp32 logits -> identical softmax/top-k semantics as the
// reference. Last block to finish resets the flag queue for the next replay.
// ---------------------------------------------------------------------------
__global__ __launch_bounds__(256)
void router_fix(const float* __restrict__ x, const float* __restrict__ w,
                float* __restrict__ outw, float* __restrict__ outi) {
    __shared__ double qs[4][EE];
    __shared__ float  ls[EE];

    int n = g_nflag;
    if (n > NTOK) n = NTOK;              // bounds-guarded
    const int e = threadIdx.x & 63;
    const int q = threadIdx.x >> 6;      // d-quarter 0..3

    for (int i = blockIdx.x; i < n; i += gridDim.x) {
        const int tok = g_flags[i];
        const float* xr = x + (size_t)tok * DD + q * (DD / 4);
        const float* wr = w + (size_t)(q * (DD / 4)) * EE + e;

        double a0 = 0.0, a1 = 0.0, a2 = 0.0, a3 = 0.0;
#pragma unroll 8
        for (int d = 0; d < DD / 4; d += 4) {
            a0 = fma((double)__ldg(xr + d + 0), (double)__ldg(wr + (size_t)(d + 0) * EE), a0);
            a1 = fma((double)__ldg(xr + d + 1), (double)__ldg(wr + (size_t)(d + 1) * EE), a1);
            a2 = fma((double)__ldg(xr + d + 2), (double)__ldg(wr + (size_t)(d + 2) * EE), a2);
            a3 = fma((double)__ldg(xr + d + 3), (double)__ldg(wr + (size_t)(d + 3) * EE), a3);
        }
        qs[q][e] = (a0 + a1) + (a2 + a3);
        __syncthreads();
        if (threadIdx.x < EE) {
            double t = ((qs[0][e] + qs[1][e]) + qs[2][e]) + qs[3][e];
            ls[e] = (float)t;
        }
        __syncthreads();
        if (threadIdx.x < 32)
            warp_topk_token(ls, tok, outw, outi, false);
        __syncthreads();
    }

    // last block to finish resets the queue (replaces the reset kernel)
    if (threadIdx.x == 0) {
        __threadfence();
        int d = atomicAdd(&g_done, 1);
        if (d == (int)gridDim.x - 1) {
            g_nflag = 0;
            g_done  = 0;
        }
    }
}

// ---------------------------------------------------------------------------
extern "C" void kernel_launch(void* const* d_in, const int* in_sizes, int n_in,
                              void* d_out, int out_size) {
    const float* x = (const float*)d_in[0];   // (4, 8192, 2048) f32
    const float* w = (const float*)d_in[1];   // (2048, 64) f32
    float* out  = (float*)d_out;
    float* outw = out;                          // weights: 32768*8
    float* outi = out + (size_t)NTOK * KTOP;    // indices (as float)

    router_gemm<<<NTOK / BM, TPB>>>(x, w, outw, outi);
    router_fix<<<128, 256>>>(x, w, outw, outi);
}